// round 4
// baseline (speedup 1.0000x reference)
#include <cuda_runtime.h>

// PhysicsEngine: B=8, NL=128, NP=8192 pairwise soft-core energy -> 3 scalars/batch.
// Single fused kernel; inner loop uses raw MUFU instructions via inline PTX so no
// libm range-reduction/fixup code inflates the issue-slot count.

#define NB 8
#define NL 128
#define NP 8192
#define CHUNK 32
#define NCHUNK (NP / CHUNK)   // 256

__device__ float g_part[NB * NCHUNK * 5];
__device__ unsigned g_count = 0;

__device__ __forceinline__ float f_rsq(float x) {
    float y; asm("rsqrt.approx.f32 %0, %1;" : "=f"(y) : "f"(x)); return y;
}
__device__ __forceinline__ float f_ex2(float x) {
    float y; asm("ex2.approx.f32 %0, %1;" : "=f"(y) : "f"(x)); return y;
}
__device__ __forceinline__ float f_rcp(float x) {
    float y; asm("rcp.approx.f32 %0, %1;" : "=f"(y) : "f"(x)); return y;
}

__global__ __launch_bounds__(NL, 12) void pe_fused_kernel(
    const float* __restrict__ pos_L, const float* __restrict__ pos_P,
    const float* __restrict__ q_L,   const float* __restrict__ q_P,
    const float* __restrict__ x_L,   const float* __restrict__ x_P,
    const float* __restrict__ vdw_radii, const float* __restrict__ epsilon,
    float* __restrict__ out)
{
    const int c = blockIdx.x;            // protein chunk
    const int b = blockIdx.y;            // batch
    const int l = threadIdx.x;           // ligand index

    // ---- stage protein chunk into SMEM (packed) ----
    __shared__ float4 sp[CHUNK];   // x, y, z, q
    __shared__ float2 sr[CHUNK];   // radius, x0
    if (threadIdx.x < CHUNK) {
        const int p = c * CHUNK + threadIdx.x;
        const float4 xp = *(const float4*)(x_P + ((size_t)b * NP + p) * 4);
        float4 v;
        v.x = pos_P[((size_t)b * NP + p) * 3 + 0];
        v.y = pos_P[((size_t)b * NP + p) * 3 + 1];
        v.z = pos_P[((size_t)b * NP + p) * 3 + 2];
        v.w = q_P[b * NP + p];
        sp[threadIdx.x] = v;
        float2 r;
        r.x = fmaf(xp.x, 1.7f, fmaf(xp.y, 1.55f, fmaf(xp.z, 1.52f, xp.w * 1.8f)));
        r.y = xp.x;
        sr[threadIdx.x] = r;
    }

    // ---- per-ligand derived quantities ----
    const float* xl = x_L + ((size_t)b * NL + l) * 9;
    float radL = 0.f, epsd = 0.f;
#pragma unroll
    for (int k = 0; k < 9; k++) {
        float x = xl[k];
        radL = fmaf(x, vdw_radii[k], radL);
        epsd = fmaf(x, epsilon[k],   epsd);
    }
    epsd = fmaxf(epsd, 0.f);
    const float c4   = 4.f * sqrtf(fmaf(epsd, 0.15f, 1e-8f));  // 4*eps_ij
    const float lx   = pos_L[((size_t)b * NL + l) * 3 + 0];
    const float ly   = pos_L[((size_t)b * NL + l) * 3 + 1];
    const float lz   = pos_L[((size_t)b * NL + l) * 3 + 2];
    const float ql83 = 83.015f * q_L[b * NL + l];              // 332.06/4 * q_L
    const float xl0  = xl[0];

    __syncthreads();

    float s_main = 0.f, s_diff = 0.f, s_hsa = 0.f, s_pauli = 0.f, s_ghost = 0.f;

#pragma unroll 8
    for (int j = 0; j < CHUNK; j++) {
        const float4 p = sp[j];
        const float2 r = sr[j];
        const float dx = lx - p.x;
        const float dy = ly - p.y;
        const float dz = lz - p.z;
        const float dsq = fmaf(dx, dx, fmaf(dy, dy, dz * dz));

        const float t    = dsq + 1e-8f;
        const float invd = f_rsq(t);
        const float dist = t * invd;                  // sqrt(dsq + 1e-8)

        const float sigma = radL + r.x;
        const float ssq   = fmaf(sigma, sigma, t);
        const float invs  = f_rsq(ssq);               // 1/soft_dist

        const float e_elec = ql83 * p.w * invs;

        // ratio = sigma/soft_dist <= 1 always (min(.,5) never binds)
        const float ratio = sigma * invs;
        const float r2 = ratio * ratio;
        const float r6 = r2 * r2 * r2;
        const float evr = c4 * fmaf(r6, r6, -r6);     // e_vdw_raw in [-0.52, 0]
        // softplus(evr+10)-10 = evr + exp(-(evr+10)) (log1p linearization, err<1e-9)
        const float ex = f_ex2(fmaf(evr, -1.442695041f, -14.42695041f));
        // em = exp(2*dist - 24); mask = 1/(1+em); em=inf far away -> R=0, mask=0
        const float em = f_ex2(fmaf(dist, 2.885390082f, -34.63068049f));

        // hsa_term = 1/A with A = 1 + (d/4)^4 = 1 + dsq^2/256 (no dist dependency)
        const float A  = fmaf(dsq * dsq, 0.00390625f, 1.f);
        // single RCP serves both: R = 1/((1+em)*A) = hsa*mask ; mask = R*A
        const float R    = f_rcp(A * (1.f + em));
        const float mask = R * A;

        s_main = fmaf(e_elec + evr + ex, mask, s_main);
        s_diff = fmaf(ex, mask, s_diff);
        s_hsa  = fmaf(xl0 * r.y, R, s_hsa);

        const float ov = fmaxf(fmaf(sigma, 0.6f, -dist), 0.f);
        s_pauli = fmaf(ov, ov, s_pauli);
        const float gh = fmaxf(0.5f - dist, 0.f);
        s_ghost = fmaf(gh, gh, s_ghost);
    }

    // ---- deterministic block reduction ----
    float v[5] = {s_main, s_diff, s_hsa, s_pauli, s_ghost};
#pragma unroll
    for (int k = 0; k < 5; k++) {
#pragma unroll
        for (int off = 16; off > 0; off >>= 1)
            v[k] += __shfl_down_sync(0xffffffffu, v[k], off);
    }
    __shared__ float wred[4][5];
    const int wid = threadIdx.x >> 5, lane = threadIdx.x & 31;
    if (lane == 0) {
#pragma unroll
        for (int k = 0; k < 5; k++) wred[wid][k] = v[k];
    }
    __syncthreads();
    if (threadIdx.x == 0) {
#pragma unroll
        for (int k = 0; k < 5; k++)
            g_part[(b * NCHUNK + c) * 5 + k] =
                wred[0][k] + wred[1][k] + wred[2][k] + wred[3][k];
    }

    // ---- last block finalizes (threadfence reduction pattern) ----
    __shared__ bool is_last;
    if (threadIdx.x == 0) {
        __threadfence();
        unsigned done = atomicAdd(&g_count, 1u);
        is_last = (done == (unsigned)(gridDim.x * gridDim.y) - 1u);
    }
    __syncthreads();
    if (!is_last) return;

    __shared__ float acc[NB][5];
    for (int task = wid; task < NB * 5; task += 4) {
        const int tb = task / 5, tk = task % 5;
        float s = 0.f;
#pragma unroll
        for (int cc = lane; cc < NCHUNK; cc += 32)
            s += g_part[(tb * NCHUNK + cc) * 5 + tk];
#pragma unroll
        for (int off = 16; off > 0; off >>= 1)
            s += __shfl_down_sync(0xffffffffu, s, off);
        if (lane == 0) acc[tb][tk] = s;
    }
    __syncthreads();
    if (threadIdx.x < NB) {
        const int w = threadIdx.x;
        const float s_m = acc[w][0], s_d = acc[w][1], s_h = acc[w][2],
                    s_p = acc[w][3], s_g = acc[w][4];
        const float e_hsa5  = -2.5f * s_h;                    // 5 * (-0.5 * s_hsa)
        const float e_pauli = 11.920292202211755f * s_p;      // 100*sigmoid(-2)
        const float e_ghost = 500.f * s_g;

        out[w] = s_m + e_hsa5 + e_pauli + e_ghost;            // e_raw

        const float e_hard = fminf(e_pauli + e_ghost, 10000.f);
        out[8 + w] = e_hard;

        float log_soft = (s_m - s_d) + e_hsa5;
        float e_soft_final = fminf(fmaxf(log_soft, -500.f), 5000.f);
        out[16 + w] = fminf(e_soft_final + e_hard, 1000000.f);
    }
    if (threadIdx.x == 0) g_count = 0;   // reset for next graph replay
}

extern "C" void kernel_launch(void* const* d_in, const int* in_sizes, int n_in,
                              void* d_out, int out_size)
{
    const float* pos_L = (const float*)d_in[0];
    const float* pos_P = (const float*)d_in[1];
    const float* q_L   = (const float*)d_in[2];
    const float* q_P   = (const float*)d_in[3];
    const float* x_L   = (const float*)d_in[4];
    const float* x_P   = (const float*)d_in[5];
    const float* vdw   = (const float*)d_in[6];
    const float* eps   = (const float*)d_in[7];

    dim3 grid(NCHUNK, NB);
    pe_fused_kernel<<<grid, NL>>>(pos_L, pos_P, q_L, q_P, x_L, x_P, vdw, eps,
                                  (float*)d_out);
}

// round 5
// speedup vs baseline: 1.0918x; 1.0918x over previous
#include <cuda_runtime.h>

// PhysicsEngine: B=8, NL=128, NP=8192 pairwise soft-core energy -> 3 scalars/batch.
// f32x2-packed inner loop (2 protein atoms per FMA instruction) — Blackwell dual
// FP32 datapath via PTX fma/add/mul.rn.f32x2. SMEM staged as pair-SoA longlong2.

#define NB 8
#define NL 128
#define NP 8192
#define CHUNK 32
#define NCHUNK (NP / CHUNK)   // 256
#define NPAIR (CHUNK / 2)     // 16

typedef unsigned long long u64;

__device__ float g_part[NB * NCHUNK * 5];
__device__ unsigned g_count = 0;

__device__ __forceinline__ u64 pk(float l, float h) {
    u64 r; asm("mov.b64 %0,{%1,%2};" : "=l"(r) : "f"(l), "f"(h)); return r;
}
__device__ __forceinline__ float f2lo(u64 a) {
    float f; asm("{\n\t.reg .b32 h;\n\tmov.b64 {%0,h},%1;\n\t}" : "=f"(f) : "l"(a)); return f;
}
__device__ __forceinline__ float f2hi(u64 a) {
    float f; asm("{\n\t.reg .b32 l;\n\tmov.b64 {l,%0},%1;\n\t}" : "=f"(f) : "l"(a)); return f;
}
__device__ __forceinline__ u64 f2add(u64 a, u64 b) {
    u64 d; asm("add.rn.f32x2 %0,%1,%2;" : "=l"(d) : "l"(a), "l"(b)); return d;
}
__device__ __forceinline__ u64 f2mul(u64 a, u64 b) {
    u64 d; asm("mul.rn.f32x2 %0,%1,%2;" : "=l"(d) : "l"(a), "l"(b)); return d;
}
__device__ __forceinline__ u64 f2fma(u64 a, u64 b, u64 c) {
    u64 d; asm("fma.rn.f32x2 %0,%1,%2,%3;" : "=l"(d) : "l"(a), "l"(b), "l"(c)); return d;
}
__device__ __forceinline__ float f_rsq(float x) {
    float y; asm("rsqrt.approx.f32 %0,%1;" : "=f"(y) : "f"(x)); return y;
}
__device__ __forceinline__ float f_ex2(float x) {
    float y; asm("ex2.approx.f32 %0,%1;" : "=f"(y) : "f"(x)); return y;
}
__device__ __forceinline__ float f_rcp(float x) {
    float y; asm("rcp.approx.f32 %0,%1;" : "=f"(y) : "f"(x)); return y;
}
__device__ __forceinline__ u64 f2rsq(u64 a) { return pk(f_rsq(f2lo(a)), f_rsq(f2hi(a))); }
__device__ __forceinline__ u64 f2ex2(u64 a) { return pk(f_ex2(f2lo(a)), f_ex2(f2hi(a))); }
__device__ __forceinline__ u64 f2rcp(u64 a) { return pk(f_rcp(f2lo(a)), f_rcp(f2hi(a))); }
__device__ __forceinline__ u64 bc(float v) { return pk(v, v); }

__global__ __launch_bounds__(NL) void pe_fused_kernel(
    const float* __restrict__ pos_L, const float* __restrict__ pos_P,
    const float* __restrict__ q_L,   const float* __restrict__ q_P,
    const float* __restrict__ x_L,   const float* __restrict__ x_P,
    const float* __restrict__ vdw_radii, const float* __restrict__ epsilon,
    float* __restrict__ out)
{
    const int c = blockIdx.x;            // protein chunk
    const int b = blockIdx.y;            // batch
    const int l = threadIdx.x;           // ligand index

    // ---- stage protein chunk into SMEM as pair-SoA (coords pre-negated) ----
    __shared__ longlong2 sA[NPAIR];      // {(-px0,-px1), (-py0,-py1)}
    __shared__ longlong2 sB[NPAIR];      // {(-pz0,-pz1), ( q0,  q1)}
    __shared__ longlong2 sC[NPAIR];      // {(rad0,rad1), ( x00, x01)}
    if (threadIdx.x < CHUNK) {
        const int p = c * CHUNK + threadIdx.x;
        const float4 xp = *(const float4*)(x_P + ((size_t)b * NP + p) * 4);
        const float rad = fmaf(xp.x, 1.7f, fmaf(xp.y, 1.55f, fmaf(xp.z, 1.52f, xp.w * 1.8f)));
        const int jj = threadIdx.x >> 1, h = threadIdx.x & 1;
        float* a0 = (float*)&sA[jj];
        float* b0 = (float*)&sB[jj];
        float* c0 = (float*)&sC[jj];
        a0[h]     = -pos_P[((size_t)b * NP + p) * 3 + 0];
        a0[2 + h] = -pos_P[((size_t)b * NP + p) * 3 + 1];
        b0[h]     = -pos_P[((size_t)b * NP + p) * 3 + 2];
        b0[2 + h] = q_P[b * NP + p];
        c0[h]     = rad;
        c0[2 + h] = xp.x;
    }

    // ---- per-ligand derived quantities ----
    const float* xl = x_L + ((size_t)b * NL + l) * 9;
    float radL = 0.f, epsd = 0.f;
#pragma unroll
    for (int k = 0; k < 9; k++) {
        float x = xl[k];
        radL = fmaf(x, vdw_radii[k], radL);
        epsd = fmaf(x, epsilon[k],   epsd);
    }
    epsd = fmaxf(epsd, 0.f);
    const u64 C4   = bc(4.f * sqrtf(fmaf(epsd, 0.15f, 1e-8f)));   // 4*eps_ij
    const u64 LX   = bc(pos_L[((size_t)b * NL + l) * 3 + 0]);
    const u64 LY   = bc(pos_L[((size_t)b * NL + l) * 3 + 1]);
    const u64 LZ   = bc(pos_L[((size_t)b * NL + l) * 3 + 2]);
    const u64 QL   = bc(83.015f * q_L[b * NL + l]);               // 332.06/4 * q_L
    const u64 XL0  = bc(xl[0]);
    const u64 RADL = bc(radL);

    // packed constants
    const u64 E8   = bc(1e-8f);
    const u64 ONE  = bc(1.f);
    const u64 NEG1 = bc(-1.f);
    const u64 HALF = bc(0.5f);
    const u64 P06  = bc(0.6f);
    const u64 I256 = bc(0.00390625f);
    const u64 K1   = bc(2.8853900817779268f);     // 2*log2(e)
    const u64 K2   = bc(-34.624680981335122f);    // -24*log2(e)
    // exp(-(evr+10)) ~= e^-10 * (1 - evr + evr^2/2 - evr^3/6), evr in [-0.52, 0]
    const u64 A3   = bc(-7.566654960414142e-06f); // -e^-10/6
    const u64 A2   = bc( 2.2699964881242427e-05f);//  e^-10/2
    const u64 A1c  = bc(-4.5399929762484854e-05f);// -e^-10
    const u64 A0   = bc( 4.5399929762484854e-05f);//  e^-10

    __syncthreads();

    u64 s_main = 0ull, s_diff = 0ull, s_hsa = 0ull;   // packed accumulators
    float sp_l = 0.f, sp_h = 0.f, sg_l = 0.f, sg_h = 0.f;

#pragma unroll 4
    for (int jj = 0; jj < NPAIR; jj++) {
        const longlong2 va = sA[jj];
        const longlong2 vb = sB[jj];
        const longlong2 vc = sC[jj];
        const u64 npx = (u64)va.x, npy = (u64)va.y;
        const u64 npz = (u64)vb.x, q2  = (u64)vb.y;
        const u64 rad2 = (u64)vc.x, x02 = (u64)vc.y;

        const u64 dx = f2add(LX, npx);
        const u64 dy = f2add(LY, npy);
        const u64 dz = f2add(LZ, npz);
        u64 t = f2fma(dz, dz, E8);
        t = f2fma(dy, dy, t);
        t = f2fma(dx, dx, t);                    // dsq + 1e-8

        const u64 invd = f2rsq(t);
        const u64 dist = f2mul(t, invd);         // sqrt(dsq + 1e-8)

        const u64 sigma = f2add(RADL, rad2);
        const u64 ssq   = f2fma(sigma, sigma, t);
        const u64 invs  = f2rsq(ssq);            // 1/soft_dist

        const u64 eel = f2mul(f2mul(QL, q2), invs);

        // ratio = sigma/soft_dist <= 1 always (min(.,5) never binds)
        const u64 ratio = f2mul(sigma, invs);
        const u64 r2 = f2mul(ratio, ratio);
        const u64 r4 = f2mul(r2, r2);
        const u64 r6 = f2mul(r4, r2);
        const u64 r6m1 = f2add(r6, NEG1);
        const u64 evr  = f2mul(f2mul(r6, r6m1), C4);   // e_vdw_raw in [-0.52, 0]

        // ex = exp(-(evr+10)) via cubic (err < 0.3% of a ~5e-5 term)
        u64 ex = f2fma(evr, A3, A2);
        ex = f2fma(evr, ex, A1c);
        ex = f2fma(evr, ex, A0);

        // em = exp(2*dist - 24); far away em=inf -> R=0, mask=0 (matches ref)
        const u64 em = f2ex2(f2fma(dist, K1, K2));

        // A = 1 + dsq^2/256 ; single RCP: R = 1/(A*(1+em)) = hsa*mask ; mask = R*A
        const u64 d4  = f2mul(t, t);
        const u64 Ah  = f2fma(d4, I256, ONE);
        const u64 R   = f2rcp(f2mul(Ah, f2add(em, ONE)));
        const u64 mask = f2mul(R, Ah);

        const u64 term = f2add(f2add(eel, evr), ex);
        s_main = f2fma(term, mask, s_main);
        s_diff = f2fma(ex, mask, s_diff);
        s_hsa  = f2fma(f2mul(XL0, x02), R, s_hsa);

        // pauli: max(0.6*sigma - dist, 0)^2 ; ghost: max(0.5 - dist, 0)^2
        const u64 nd  = f2mul(dist, NEG1);
        const u64 ovp = f2fma(sigma, P06, nd);
        const u64 ghp = f2add(nd, HALF);
        const float ovl = fmaxf(f2lo(ovp), 0.f), ovh = fmaxf(f2hi(ovp), 0.f);
        sp_l = fmaf(ovl, ovl, sp_l); sp_h = fmaf(ovh, ovh, sp_h);
        const float gl = fmaxf(f2lo(ghp), 0.f), gh = fmaxf(f2hi(ghp), 0.f);
        sg_l = fmaf(gl, gl, sg_l); sg_h = fmaf(gh, gh, sg_h);
    }

    // ---- combine packed halves, then deterministic block reduction ----
    float v[5];
    v[0] = f2lo(s_main) + f2hi(s_main);
    v[1] = f2lo(s_diff) + f2hi(s_diff);
    v[2] = f2lo(s_hsa)  + f2hi(s_hsa);
    v[3] = sp_l + sp_h;
    v[4] = sg_l + sg_h;
#pragma unroll
    for (int k = 0; k < 5; k++) {
#pragma unroll
        for (int off = 16; off > 0; off >>= 1)
            v[k] += __shfl_down_sync(0xffffffffu, v[k], off);
    }
    __shared__ float wred[4][5];
    const int wid = threadIdx.x >> 5, lane = threadIdx.x & 31;
    if (lane == 0) {
#pragma unroll
        for (int k = 0; k < 5; k++) wred[wid][k] = v[k];
    }
    __syncthreads();
    if (threadIdx.x == 0) {
#pragma unroll
        for (int k = 0; k < 5; k++)
            g_part[(b * NCHUNK + c) * 5 + k] =
                wred[0][k] + wred[1][k] + wred[2][k] + wred[3][k];
    }

    // ---- last block finalizes ----
    __shared__ bool is_last;
    if (threadIdx.x == 0) {
        __threadfence();
        unsigned done = atomicAdd(&g_count, 1u);
        is_last = (done == (unsigned)(gridDim.x * gridDim.y) - 1u);
    }
    __syncthreads();
    if (!is_last) return;

    __shared__ float acc[NB][5];
    for (int task = wid; task < NB * 5; task += 4) {
        const int tb = task / 5, tk = task % 5;
        float s = 0.f;
#pragma unroll
        for (int cc = lane; cc < NCHUNK; cc += 32)
            s += g_part[(tb * NCHUNK + cc) * 5 + tk];
#pragma unroll
        for (int off = 16; off > 0; off >>= 1)
            s += __shfl_down_sync(0xffffffffu, s, off);
        if (lane == 0) acc[tb][tk] = s;
    }
    __syncthreads();
    if (threadIdx.x < NB) {
        const int w = threadIdx.x;
        const float s_m = acc[w][0], s_d = acc[w][1], s_h = acc[w][2],
                    s_p = acc[w][3], s_g = acc[w][4];
        const float e_hsa5  = -2.5f * s_h;                    // 5 * (-0.5 * s_hsa)
        const float e_pauli = 11.920292202211755f * s_p;      // 100*sigmoid(-2)
        const float e_ghost = 500.f * s_g;

        out[w] = s_m + e_hsa5 + e_pauli + e_ghost;            // e_raw

        const float e_hard = fminf(e_pauli + e_ghost, 10000.f);
        out[8 + w] = e_hard;

        float log_soft = (s_m - s_d) + e_hsa5;
        float e_soft_final = fminf(fmaxf(log_soft, -500.f), 5000.f);
        out[16 + w] = fminf(e_soft_final + e_hard, 1000000.f);
    }
    if (threadIdx.x == 0) g_count = 0;   // reset for next graph replay
}

extern "C" void kernel_launch(void* const* d_in, const int* in_sizes, int n_in,
                              void* d_out, int out_size)
{
    const float* pos_L = (const float*)d_in[0];
    const float* pos_P = (const float*)d_in[1];
    const float* q_L   = (const float*)d_in[2];
    const float* q_P   = (const float*)d_in[3];
    const float* x_L   = (const float*)d_in[4];
    const float* x_P   = (const float*)d_in[5];
    const float* vdw   = (const float*)d_in[6];
    const float* eps   = (const float*)d_in[7];

    dim3 grid(NCHUNK, NB);
    pe_fused_kernel<<<grid, NL>>>(pos_L, pos_P, q_L, q_P, x_L, x_P, vdw, eps,
                                  (float*)d_out);
}